// round 3
// baseline (speedup 1.0000x reference)
#include <cuda_runtime.h>
#include <cstddef>

// Problem constants (fixed by the reference)
constexpr int CB   = 64;    // batch
constexpr int CP   = 2048;  // points
constexpr int CK   = 16;    // neighbors
constexpr int CDIM = 3;
constexpr int CNC  = 16;    // rbf centers
constexpr int CSFD = 64;    // spatial feature dim
constexpr int COUT = 64;    // output features

constexpr int PTS     = 32;   // points per block
constexpr int THREADS = 256;  // 8 warps, 4 points per warp

__global__ __launch_bounds__(THREADS)
void rbfn_fused_kernel(const float* __restrict__ features,
                       const float* __restrict__ spatial,
                       const float* __restrict__ centers,
                       const float* __restrict__ rbfw,
                       const float* __restrict__ w,
                       float* __restrict__ out)
{
    __shared__ float w_sh[CSFD * COUT];     // 16 KB : w[b] slice
    __shared__ float rbfn_sh[CNC * CSFD];   // 4 KB
    __shared__ float cen_sh[CDIM * CNC];    // 192 B : centers (dim-major)
    __shared__ float x_sh[PTS * CSFD];      // 8 KB : fused x = fl * sp_sum

    const int tid = threadIdx.x;
    const int b   = blockIdx.y;
    const int p0  = blockIdx.x * PTS;

    // ---- stage per-batch weight slice + small constants into smem ----
    {
        const float4* wsrc = reinterpret_cast<const float4*>(w + (size_t)b * CSFD * COUT);
        float4* wdst = reinterpret_cast<float4*>(w_sh);
        #pragma unroll
        for (int i = 0; i < (CSFD * COUT / 4) / THREADS; i++)   // 4 iters
            wdst[tid + i * THREADS] = wsrc[tid + i * THREADS];

        const float4* rsrc = reinterpret_cast<const float4*>(rbfw);
        reinterpret_cast<float4*>(rbfn_sh)[tid & 255] = rsrc[tid & 255]; // 256 float4 = 1024 f

        if (tid < CDIM * CNC) cen_sh[tid] = centers[tid];
    }
    __syncthreads();

    // ---- Phase 1: per-warp, 4 points each. Produce x_sh[pt][s]. ----
    const int warp = tid >> 5;
    const int lane = tid & 31;
    const int cg   = lane & 15;   // column group (s = 4*cg..4*cg+3) AND center id
    const int half = lane >> 4;   // which half of the K rows this lane covers

    const float c0 = cen_sh[0 * CNC + cg];
    const float c1 = cen_sh[1 * CNC + cg];
    const float c2 = cen_sh[2 * CNC + cg];

    #pragma unroll
    for (int j = 0; j < 4; j++) {
        const int    pt   = warp * 4 + j;
        const size_t pidx = (size_t)b * CP + p0 + pt;

        // --- spatial sum over K: 1024 contiguous floats, float4-coalesced ---
        const float4* spv = reinterpret_cast<const float4*>(spatial + pidx * (CK * CSFD));
        float sx = 0.f, sy = 0.f, sz = 0.f, sw = 0.f;
        #pragma unroll
        for (int i = 0; i < 8; i++) {
            // idx = i*32+lane -> row k = idx>>4, col group = lane&15 (fixed per lane)
            float4 v = spv[i * 32 + lane];
            sx += v.x; sy += v.y; sz += v.z; sw += v.w;
        }
        // lanes t and t^16 hold the two K-halves of the same column group
        sx += __shfl_xor_sync(0xffffffffu, sx, 16);
        sy += __shfl_xor_sync(0xffffffffu, sy, 16);
        sz += __shfl_xor_sync(0xffffffffu, sz, 16);
        sw += __shfl_xor_sync(0xffffffffu, sw, 16);

        // --- RBF: each lane sums exp(-||f_k - c_cg||^2 / 0.08) over its 8 k's ---
        const float* fb = features + pidx * (CK * CDIM);
        float racc = 0.f;
        #pragma unroll
        for (int i = 0; i < 8; i++) {
            const int k = 2 * i + half;
            float f0 = fb[k * 3 + 0];
            float f1 = fb[k * 3 + 1];
            float f2 = fb[k * 3 + 2];
            float d0 = f0 - c0, d1 = f1 - c1, d2 = f2 - c2;
            float dn2 = d0 * d0 + d1 * d1 + d2 * d2;
            racc += __expf(dn2 * -12.5f);   // 1/0.08 = 12.5
        }
        racc += __shfl_xor_sync(0xffffffffu, racc, 16);
        // now lane c (and c+16) holds rbf_sum for center c

        // --- feature layer for s = 4*cg..4*cg+3, fused with spatial product ---
        float flx = 0.f, fly = 0.f, flz = 0.f, flw = 0.f;
        #pragma unroll
        for (int c = 0; c < CNC; c++) {
            float rv  = __shfl_sync(0xffffffffu, racc, c);
            float4 wv = reinterpret_cast<const float4*>(rbfn_sh)[c * 16 + cg];
            flx += rv * wv.x; fly += rv * wv.y; flz += rv * wv.z; flw += rv * wv.w;
        }
        if (half == 0) {
            float4 xv;
            xv.x = flx * sx; xv.y = fly * sy; xv.z = flz * sz; xv.w = flw * sw;
            reinterpret_cast<float4*>(x_sh)[pt * 16 + cg] = xv;
        }
    }
    __syncthreads();

    // ---- Phase 2: out[pt][o] = sum_s x[pt][s] * w_sh[s][o] ----
    // thread -> (o = tid&63, point group pg = tid>>6 handling 8 points)
    const int o  = tid & 63;
    const int pg = tid >> 6;

    float acc[8];
    #pragma unroll
    for (int jj = 0; jj < 8; jj++) acc[jj] = 0.f;

    #pragma unroll
    for (int sq = 0; sq < CSFD / 4; sq++) {
        // conflict-free: within a warp o is 32 consecutive values
        float w0 = w_sh[(4 * sq + 0) * COUT + o];
        float w1 = w_sh[(4 * sq + 1) * COUT + o];
        float w2 = w_sh[(4 * sq + 2) * COUT + o];
        float w3 = w_sh[(4 * sq + 3) * COUT + o];
        #pragma unroll
        for (int jj = 0; jj < 8; jj++) {
            // warp-uniform address -> smem broadcast
            float4 xv = reinterpret_cast<const float4*>(x_sh)[(pg * 8 + jj) * 16 + sq];
            acc[jj] += xv.x * w0 + xv.y * w1 + xv.z * w2 + xv.w * w3;
        }
    }

    float* ob = out + ((size_t)b * CP + p0) * COUT;
    #pragma unroll
    for (int jj = 0; jj < 8; jj++)
        ob[(size_t)(pg * 8 + jj) * COUT + o] = acc[jj];
}

extern "C" void kernel_launch(void* const* d_in, const int* in_sizes, int n_in,
                              void* d_out, int out_size)
{
    const float* features = (const float*)d_in[0];
    const float* spatial  = (const float*)d_in[1];
    const float* centers  = (const float*)d_in[2];
    const float* rbfw     = (const float*)d_in[3];
    const float* w        = (const float*)d_in[4];
    // d_in[5] is K (=16), fixed at compile time
    float* out = (float*)d_out;

    dim3 grid(CP / PTS, CB);
    rbfn_fused_kernel<<<grid, THREADS>>>(features, spatial, centers, rbfw, w, out);
}